// round 1
// baseline (speedup 1.0000x reference)
#include <cuda_runtime.h>

// ---------------- Problem constants (fixed by the reference) ----------------
#define B_ROWS   2048      // batch
#define TOTAL_D  4096      // S + I + O
#define S_D      1024
#define O_OFFSET 3072      // S + I
#define IN_D     1024
#define NC_D     1000
#define OD_D     1024      // O_DIM

// ---------------- Device scratch (allocation-free contract) ----------------
__device__ float g_E  [B_ROWS * S_D];      // E = x@Wp^T + bp (pre-relu, reused at t=5)
__device__ float g_Za [B_ROWS * TOTAL_D];  // ping
__device__ float g_Zb [B_ROWS * TOTAL_D];  // pong
__device__ float g_WpT[IN_D  * S_D];       // Wp^T  [IN_D x S_D]
__device__ float g_WoT[OD_D  * NC_D];      // Wo^T  [OD_D x NC_D]

// ---------------- Transpose: out[C x R] from in[R x C] ----------------
__global__ void transpose_kernel(const float* __restrict__ in,
                                 float* __restrict__ out, int R, int C) {
    __shared__ float tile[32][33];
    int c = blockIdx.x * 32 + threadIdx.x;
    int r = blockIdx.y * 32 + threadIdx.y;
    if (r < R && c < C) tile[threadIdx.y][threadIdx.x] = in[(size_t)r * C + c];
    __syncthreads();
    int orow = blockIdx.x * 32 + threadIdx.y;  // index into C-dim
    int ocol = blockIdx.y * 32 + threadIdx.x;  // index into R-dim
    if (orow < C && ocol < R) out[(size_t)orow * R + ocol] = tile[threadIdx.x][threadIdx.y];
}

// ---------------- SGEMM: C[M,N] = op(A)[M,K] @ B[K,N] (+bias)(+inj)(relu) ----
// A row-major (lda), B row-major (ldb), C row-major (ldc).
// RELU_A : relu applied to A elements on load (Z1 = relu(E) trick)
// INJECT : C[r,c] += inj[r*inj_ld + c] for c < S_D, before relu (t=5)
template<bool RELU_A, bool DO_RELU, bool HAS_BIAS, bool INJECT>
__global__ __launch_bounds__(256, 2)
void sgemm_kernel(const float* __restrict__ A, int lda,
                  const float* __restrict__ B, int ldb,
                  float* __restrict__ C, int ldc,
                  int M, int N, int K,
                  const float* __restrict__ bias,
                  const float* __restrict__ inj, int inj_ld)
{
    __shared__ float As[8][128];
    __shared__ float Bs[8][128];

    const int tid = threadIdx.x;
    const int tx = tid & 15;        // 0..15 -> N micro
    const int ty = tid >> 4;        // 0..15 -> M micro
    const int bx = blockIdx.x;      // N tile
    const int by = blockIdx.y;      // M tile

    // A-tile load map: 128 rows x 8 cols, one float4 per thread
    const int aRow = tid >> 1;             // 0..127
    const int aCol = (tid & 1) << 2;       // 0 or 4
    // B-tile load map: 8 rows x 128 cols, one float4 per thread
    const int bRow = tid >> 5;             // 0..7
    const int bCol = (tid & 31) << 2;      // 0..124
    const int gBcol = bx * 128 + bCol;

    const float* Aptr = A + (size_t)(by * 128 + aRow) * lda + aCol;

    float acc[8][8];
    #pragma unroll
    for (int i = 0; i < 8; i++)
        #pragma unroll
        for (int j = 0; j < 8; j++) acc[i][j] = 0.0f;

    for (int k0 = 0; k0 < K; k0 += 8) {
        float4 av = *reinterpret_cast<const float4*>(Aptr + k0);
        if (RELU_A) {
            av.x = fmaxf(av.x, 0.0f); av.y = fmaxf(av.y, 0.0f);
            av.z = fmaxf(av.z, 0.0f); av.w = fmaxf(av.w, 0.0f);
        }
        float4 bv;
        const float* Brow = B + (size_t)(k0 + bRow) * ldb;
        if (gBcol + 3 < N) {
            bv = *reinterpret_cast<const float4*>(Brow + gBcol);
        } else {
            bv.x = (gBcol + 0 < N) ? Brow[gBcol + 0] : 0.0f;
            bv.y = (gBcol + 1 < N) ? Brow[gBcol + 1] : 0.0f;
            bv.z = (gBcol + 2 < N) ? Brow[gBcol + 2] : 0.0f;
            bv.w = (gBcol + 3 < N) ? Brow[gBcol + 3] : 0.0f;
        }

        As[aCol + 0][aRow] = av.x;
        As[aCol + 1][aRow] = av.y;
        As[aCol + 2][aRow] = av.z;
        As[aCol + 3][aRow] = av.w;
        *reinterpret_cast<float4*>(&Bs[bRow][bCol]) = bv;
        __syncthreads();

        #pragma unroll
        for (int kk = 0; kk < 8; kk++) {
            float a[8], b[8];
            *reinterpret_cast<float4*>(&a[0]) = *reinterpret_cast<const float4*>(&As[kk][ty * 8]);
            *reinterpret_cast<float4*>(&a[4]) = *reinterpret_cast<const float4*>(&As[kk][ty * 8 + 4]);
            *reinterpret_cast<float4*>(&b[0]) = *reinterpret_cast<const float4*>(&Bs[kk][tx * 8]);
            *reinterpret_cast<float4*>(&b[4]) = *reinterpret_cast<const float4*>(&Bs[kk][tx * 8 + 4]);
            #pragma unroll
            for (int i = 0; i < 8; i++)
                #pragma unroll
                for (int j = 0; j < 8; j++)
                    acc[i][j] = fmaf(a[i], b[j], acc[i][j]);
        }
        __syncthreads();
    }

    // Epilogue (cost negligible vs mainloop)
    #pragma unroll
    for (int i = 0; i < 8; i++) {
        const int row = by * 128 + ty * 8 + i;
        #pragma unroll
        for (int j = 0; j < 8; j++) {
            const int col = bx * 128 + tx * 8 + j;
            if (col < N) {
                float v = acc[i][j];
                if (HAS_BIAS) v += bias[col];
                if (INJECT && col < S_D) v += inj[(size_t)row * inj_ld + col];
                if (DO_RELU) v = fmaxf(v, 0.0f);
                C[(size_t)row * ldc + col] = v;
            }
        }
    }
}

// ---------------- Launch orchestration ----------------
extern "C" void kernel_launch(void* const* d_in, const int* in_sizes, int n_in,
                              void* d_out, int out_size)
{
    const float* x  = (const float*)d_in[0];  // [2048, 1024]
    const float* W  = (const float*)d_in[1];  // [4096, 4096]
    const float* Wp = (const float*)d_in[2];  // [1024, 1024]
    const float* bp = (const float*)d_in[3];  // [1024]
    const float* Wo = (const float*)d_in[4];  // [1000, 1024]
    const float* bo = (const float*)d_in[5];  // [1000]
    // d_in[6] = time_steps (always 10)

    float *E, *Za, *Zb, *WpT, *WoT;
    cudaGetSymbolAddress((void**)&E,   g_E);
    cudaGetSymbolAddress((void**)&Za,  g_Za);
    cudaGetSymbolAddress((void**)&Zb,  g_Zb);
    cudaGetSymbolAddress((void**)&WpT, g_WpT);
    cudaGetSymbolAddress((void**)&WoT, g_WoT);

    // Pre-transpose Wp and Wo so all GEMMs are NN row-major
    {
        dim3 th(32, 32);
        transpose_kernel<<<dim3((IN_D + 31) / 32, (S_D + 31) / 32), th>>>(Wp, WpT, S_D, IN_D);
        transpose_kernel<<<dim3((OD_D + 31) / 32, (NC_D + 31) / 32), th>>>(Wo, WoT, NC_D, OD_D);
    }

    const dim3 thr(256);

    // E = x @ Wp^T + bp   (M=2048, N=1024, K=1024)
    sgemm_kernel<false, false, true, false>
        <<<dim3(S_D / 128, B_ROWS / 128), thr>>>(
            x, IN_D, WpT, S_D, E, S_D, B_ROWS, S_D, IN_D, bp, nullptr, 0);

    // t=0 is free (Z1 = [relu(E), 0]); t=1 uses only first 1024 rows of W:
    // Za = relu( relu(E) @ W[0:1024, :] )   (M=2048, N=4096, K=1024)
    sgemm_kernel<true, true, false, false>
        <<<dim3(TOTAL_D / 128, B_ROWS / 128), thr>>>(
            E, S_D, W, TOTAL_D, Za, TOTAL_D, B_ROWS, TOTAL_D, S_D, nullptr, nullptr, 0);

    // Steps t=2..9: full GEMMs; inject E (pre-relu) at t=5
    float* cur = Za;
    float* nxt = Zb;
    for (int s = 0; s < 8; s++) {
        const int t = 2 + s;
        if (t == 5) {
            sgemm_kernel<false, true, false, true>
                <<<dim3(TOTAL_D / 128, B_ROWS / 128), thr>>>(
                    cur, TOTAL_D, W, TOTAL_D, nxt, TOTAL_D,
                    B_ROWS, TOTAL_D, TOTAL_D, nullptr, E, S_D);
        } else {
            sgemm_kernel<false, true, false, false>
                <<<dim3(TOTAL_D / 128, B_ROWS / 128), thr>>>(
                    cur, TOTAL_D, W, TOTAL_D, nxt, TOTAL_D,
                    B_ROWS, TOTAL_D, TOTAL_D, nullptr, nullptr, 0);
        }
        float* tmp = cur; cur = nxt; nxt = tmp;
    }

    // out = Z10[:, 3072:] @ Wo^T + bo   (M=2048, N=1000, K=1024)
    sgemm_kernel<false, false, true, false>
        <<<dim3((NC_D + 127) / 128, B_ROWS / 128), thr>>>(
            cur + O_OFFSET, TOTAL_D, WoT, NC_D, (float*)d_out, NC_D,
            B_ROWS, NC_D, OD_D, bo, nullptr, 0);
}

// round 3
// speedup vs baseline: 2.9609x; 2.9609x over previous
#include <cuda_runtime.h>
#include <cuda_bf16.h>
#include <cstdint>

typedef __nv_bfloat16 bf16;

// ---------------- Problem constants ----------------
#define B_ROWS   2048
#define TOTAL_D  4096
#define S_D      1024
#define O_OFF    3072
#define IN_D     1024
#define NC_D     1000
#define OD_D     1024

// ---------------- Device scratch (16B aligned for cp.async) ----------------
__device__ __align__(16) bf16  g_WT_hi[(size_t)TOTAL_D * TOTAL_D];
__device__ __align__(16) bf16  g_WT_lo[(size_t)TOTAL_D * TOTAL_D];
__device__ __align__(16) bf16  g_Wp_hi[(size_t)S_D * IN_D];
__device__ __align__(16) bf16  g_Wp_lo[(size_t)S_D * IN_D];
__device__ __align__(16) bf16  g_Wo_hi[(size_t)1024 * OD_D];   // padded to 1024 rows
__device__ __align__(16) bf16  g_Wo_lo[(size_t)1024 * OD_D];
__device__ __align__(16) bf16  g_x_hi [(size_t)B_ROWS * IN_D];
__device__ __align__(16) bf16  g_x_lo [(size_t)B_ROWS * IN_D];
__device__ __align__(16) float g_E    [(size_t)B_ROWS * S_D];  // pre-relu E (t=5 inject)
__device__ __align__(16) bf16  g_E_hi [(size_t)B_ROWS * S_D];  // relu(E) split
__device__ __align__(16) bf16  g_E_lo [(size_t)B_ROWS * S_D];
__device__ __align__(16) bf16  g_Za_hi[(size_t)B_ROWS * TOTAL_D];
__device__ __align__(16) bf16  g_Za_lo[(size_t)B_ROWS * TOTAL_D];
__device__ __align__(16) bf16  g_Zb_hi[(size_t)B_ROWS * TOTAL_D];
__device__ __align__(16) bf16  g_Zb_lo[(size_t)B_ROWS * TOTAL_D];
__device__ __align__(16) bf16  g_O_hi [(size_t)B_ROWS * OD_D];
__device__ __align__(16) bf16  g_O_lo [(size_t)B_ROWS * OD_D];

// ---------------- PTX helpers (sm_100 BASE target safe) ----------------
__device__ __forceinline__ uint32_t smem_u32(const void* p) {
    uint32_t a;
    asm("{ .reg .u64 t; cvta.to.shared.u64 t, %1; cvt.u32.u64 %0, t; }" : "=r"(a) : "l"(p));
    return a;
}
__device__ __forceinline__ void cpa16(uint32_t saddr, const void* g) {
    asm volatile("cp.async.cg.shared.global [%0], [%1], 16;" :: "r"(saddr), "l"(g));
}
__device__ __forceinline__ void cpa_commit() {
    asm volatile("cp.async.commit_group;" ::: "memory");
}
__device__ __forceinline__ void cpa_wait1() {
    asm volatile("cp.async.wait_group 1;" ::: "memory");
}
__device__ __forceinline__ void ldsm4(uint32_t* r, uint32_t addr) {
    asm volatile("ldmatrix.sync.aligned.m8n8.x4.shared.b16 {%0,%1,%2,%3}, [%4];"
                 : "=r"(r[0]), "=r"(r[1]), "=r"(r[2]), "=r"(r[3]) : "r"(addr));
}
__device__ __forceinline__ void mma16816(float* c, const uint32_t* a,
                                         uint32_t b0, uint32_t b1) {
    asm volatile(
        "mma.sync.aligned.m16n8k16.row.col.f32.bf16.bf16.f32 "
        "{%0,%1,%2,%3}, {%4,%5,%6,%7}, {%8,%9}, {%0,%1,%2,%3};"
        : "+f"(c[0]), "+f"(c[1]), "+f"(c[2]), "+f"(c[3])
        : "r"(a[0]), "r"(a[1]), "r"(a[2]), "r"(a[3]), "r"(b0), "r"(b1));
}

// Swizzled smem offset for (row r, 16B-group g) within a 128x32 bf16 tile.
// Layout: row pair (r>>1) occupies one 128B line; odd row in upper 64B;
// g XOR (r>>1)&3 -> conflict-free ldmatrix (8 rows) and cp.async stores.
__device__ __forceinline__ uint32_t swz_off(int r, int g) {
    return (uint32_t)(((r >> 1) << 7) + ((r & 1) << 6) + (((g ^ ((r >> 1) & 3)) & 3) << 4));
}

// ---------------- SMEM: 3 stages x (A hi/lo 8KB + B hi/lo 8KB each) ----------------
#define STG 32768
#define SMEM_BYTES (3 * STG)

// ---------------- GEMM: C[M,N] = (Ahi+Alo)[M,K] @ (Bhi+Blo)[N,K]^T  ----------------
// 3-way split products: Ah*Bh + Ah*Bl + Al*Bh. Fused epilogues per template.
template<bool BIAS, bool INJ, bool WF32, bool WBF16, bool RELUB>
__global__ __launch_bounds__(128, 2)
void mma_gemm(const bf16* __restrict__ Ahi, const bf16* __restrict__ Alo, int lda,
              const bf16* __restrict__ Bhi, const bf16* __restrict__ Blo, int ldb,
              int K, int Nvalid,
              float* __restrict__ outf, int ldo,
              bf16* __restrict__ ohi, bf16* __restrict__ olo, int ldh,
              const float* __restrict__ bias,
              const float* __restrict__ inj, int ldinj)
{
    extern __shared__ __align__(128) char smem[];
    const uint32_t sbase = smem_u32(smem);
    const int tid  = threadIdx.x;
    const int lane = tid & 31;
    const int wid  = tid >> 5;
    const int wm   = wid & 1;       // warp row (2)
    const int wn   = wid >> 1;      // warp col (2)
    const int bx = blockIdx.x, by = blockIdx.y;

    // per-lane ldmatrix row/group decomposition
    const int lr = lane & 7;
    const int lm = (lane >> 3) & 1; // +8 rows for matrices 1,3
    const int lg = lane >> 4;       // +1 k-group for matrices 2,3

    float acc[4][8][4];
    #pragma unroll
    for (int i = 0; i < 4; i++)
        #pragma unroll
        for (int j = 0; j < 8; j++)
            #pragma unroll
            for (int q = 0; q < 4; q++) acc[i][j][q] = 0.0f;

    const int nst = K >> 5;  // K/32

    // ---- stage prefetch: 16 cp.async of 16B per thread ----
    auto prefetch = [&](int s, int buf) {
        const uint32_t sb = sbase + buf * STG;
        const size_t k0 = (size_t)s * 32;
        #pragma unroll
        for (int i = 0; i < 4; i++) {
            const int c = i * 128 + tid;
            const int r = c >> 2, g = c & 3;
            const uint32_t so = swz_off(r, g);
            const size_t ga = (size_t)(by * 128 + r) * lda + k0 + g * 8;
            const size_t gb = (size_t)(bx * 128 + r) * ldb + k0 + g * 8;
            cpa16(sb +         so, Ahi + ga);
            cpa16(sb +  8192 + so, Alo + ga);
            cpa16(sb + 16384 + so, Bhi + gb);
            cpa16(sb + 24576 + so, Blo + gb);
        }
    };

    prefetch(0, 0); cpa_commit();
    prefetch(1, 1); cpa_commit();

    for (int s = 0; s < nst; s++) {
        const int bs = s % 3;
        cpa_wait1();
        __syncthreads();
        if (s + 2 < nst) prefetch(s + 2, (s + 2) % 3);
        cpa_commit();

        const uint32_t sA_hi = sbase + bs * STG;
        const uint32_t sA_lo = sA_hi + 8192;
        const uint32_t sB_hi = sA_hi + 16384;
        const uint32_t sB_lo = sA_hi + 24576;

        #pragma unroll
        for (int kc = 0; kc < 2; kc++) {
            const int g = kc * 2 + lg;
            // B fragments for the whole 64-wide warp tile (hi and lo)
            uint32_t bh[4][4], bl[4][4];
            #pragma unroll
            for (int nn = 0; nn < 4; nn++) {
                const int r = wn * 64 + nn * 16 + lr + lm * 8;
                const uint32_t off = swz_off(r, g);
                ldsm4(bh[nn], sB_hi + off);
                ldsm4(bl[nn], sB_lo + off);
            }
            #pragma unroll
            for (int mf = 0; mf < 4; mf++) {
                const int r = wm * 64 + mf * 16 + lr + lm * 8;
                const uint32_t off = swz_off(r, g);
                uint32_t a[4];
                ldsm4(a, sA_hi + off);      // A-hi
                #pragma unroll
                for (int nn = 0; nn < 4; nn++) {
                    mma16816(acc[mf][nn * 2 + 0], a, bh[nn][0], bh[nn][2]);
                    mma16816(acc[mf][nn * 2 + 1], a, bh[nn][1], bh[nn][3]);
                    mma16816(acc[mf][nn * 2 + 0], a, bl[nn][0], bl[nn][2]);
                    mma16816(acc[mf][nn * 2 + 1], a, bl[nn][1], bl[nn][3]);
                }
                ldsm4(a, sA_lo + off);      // A-lo (x B-hi only)
                #pragma unroll
                for (int nn = 0; nn < 4; nn++) {
                    mma16816(acc[mf][nn * 2 + 0], a, bh[nn][0], bh[nn][2]);
                    mma16816(acc[mf][nn * 2 + 1], a, bh[nn][1], bh[nn][3]);
                }
            }
        }
        __syncthreads();
    }

    // ---- epilogue: fused bias / inject / relu / split / store ----
    auto wpair = [&](int m, int n, float v0, float v1) {
        if (BIAS) {
            if (n     < Nvalid) v0 += bias[n];
            if (n + 1 < Nvalid) v1 += bias[n + 1];
        }
        if (INJ) {
            if (n     < S_D) v0 += inj[(size_t)m * ldinj + n];
            if (n + 1 < S_D) v1 += inj[(size_t)m * ldinj + n + 1];
        }
        if (WF32) {
            if (n     < Nvalid) outf[(size_t)m * ldo + n]     = v0;
            if (n + 1 < Nvalid) outf[(size_t)m * ldo + n + 1] = v1;
        }
        if (WBF16) {
            const float r0 = RELUB ? fmaxf(v0, 0.0f) : v0;
            const float r1 = RELUB ? fmaxf(v1, 0.0f) : v1;
            const bf16 h0 = __float2bfloat16(r0);
            const bf16 h1 = __float2bfloat16(r1);
            __nv_bfloat162 hv; hv.x = h0; hv.y = h1;
            __nv_bfloat162 lv;
            lv.x = __float2bfloat16(r0 - __bfloat162float(h0));
            lv.y = __float2bfloat16(r1 - __bfloat162float(h1));
            *reinterpret_cast<__nv_bfloat162*>(ohi + (size_t)m * ldh + n) = hv;
            *reinterpret_cast<__nv_bfloat162*>(olo + (size_t)m * ldh + n) = lv;
        }
    };

    const int mbase = by * 128 + wm * 64;
    const int nbase = bx * 128 + wn * 64;
    #pragma unroll
    for (int mf = 0; mf < 4; mf++) {
        #pragma unroll
        for (int nf = 0; nf < 8; nf++) {
            const int row = mbase + mf * 16 + (lane >> 2);
            const int col = nbase + nf * 8 + (lane & 3) * 2;
            wpair(row,     col, acc[mf][nf][0], acc[mf][nf][1]);
            wpair(row + 8, col, acc[mf][nf][2], acc[mf][nf][3]);
        }
    }
}

// ---------------- split-transpose W -> WT hi/lo ----------------
__global__ void k_splitT(const float* __restrict__ W,
                         bf16* __restrict__ th, bf16* __restrict__ tl) {
    __shared__ float t[32][33];
    const int x = blockIdx.x * 32 + threadIdx.x;
    const int y = blockIdx.y * 32 + threadIdx.y;
    t[threadIdx.y][threadIdx.x] = W[(size_t)y * TOTAL_D + x];
    __syncthreads();
    const int n = blockIdx.x * 32 + threadIdx.y;
    const int k = blockIdx.y * 32 + threadIdx.x;
    const float v = t[threadIdx.x][threadIdx.y];
    const bf16 h = __float2bfloat16(v);
    th[(size_t)n * TOTAL_D + k] = h;
    tl[(size_t)n * TOTAL_D + k] = __float2bfloat16(v - __bfloat162float(h));
}

// ---------------- elementwise split (zero-pad beyond nvalid) ----------------
__global__ void k_split(const float* __restrict__ in,
                        bf16* __restrict__ h, bf16* __restrict__ l,
                        int nvalid, int ntot) {
    const int i = blockIdx.x * 256 + threadIdx.x;
    if (i >= ntot) return;
    const float v = (i < nvalid) ? in[i] : 0.0f;
    const bf16 hv = __float2bfloat16(v);
    h[i] = hv;
    l[i] = __float2bfloat16(v - __bfloat162float(hv));
}

// ---------------- Orchestration ----------------
extern "C" void kernel_launch(void* const* d_in, const int* in_sizes, int n_in,
                              void* d_out, int out_size)
{
    const float* x  = (const float*)d_in[0];
    const float* W  = (const float*)d_in[1];
    const float* Wp = (const float*)d_in[2];
    const float* bp = (const float*)d_in[3];
    const float* Wo = (const float*)d_in[4];
    const float* bo = (const float*)d_in[5];

    bf16 *WTh, *WTl, *Wph, *Wpl, *Woh, *Wol, *xh, *xl, *Eh, *El;
    bf16 *Zah, *Zal, *Zbh, *Zbl, *Oh, *Ol;
    float* E;
    cudaGetSymbolAddress((void**)&WTh, g_WT_hi);
    cudaGetSymbolAddress((void**)&WTl, g_WT_lo);
    cudaGetSymbolAddress((void**)&Wph, g_Wp_hi);
    cudaGetSymbolAddress((void**)&Wpl, g_Wp_lo);
    cudaGetSymbolAddress((void**)&Woh, g_Wo_hi);
    cudaGetSymbolAddress((void**)&Wol, g_Wo_lo);
    cudaGetSymbolAddress((void**)&xh,  g_x_hi);
    cudaGetSymbolAddress((void**)&xl,  g_x_lo);
    cudaGetSymbolAddress((void**)&E,   g_E);
    cudaGetSymbolAddress((void**)&Eh,  g_E_hi);
    cudaGetSymbolAddress((void**)&El,  g_E_lo);
    cudaGetSymbolAddress((void**)&Zah, g_Za_hi);
    cudaGetSymbolAddress((void**)&Zal, g_Za_lo);
    cudaGetSymbolAddress((void**)&Zbh, g_Zb_hi);
    cudaGetSymbolAddress((void**)&Zbl, g_Zb_lo);
    cudaGetSymbolAddress((void**)&Oh,  g_O_hi);
    cudaGetSymbolAddress((void**)&Ol,  g_O_lo);

    cudaFuncSetAttribute(mma_gemm<true,  false, true,  true,  true >, cudaFuncAttributeMaxDynamicSharedMemorySize, SMEM_BYTES);
    cudaFuncSetAttribute(mma_gemm<false, false, false, true,  true >, cudaFuncAttributeMaxDynamicSharedMemorySize, SMEM_BYTES);
    cudaFuncSetAttribute(mma_gemm<false, true,  false, true,  true >, cudaFuncAttributeMaxDynamicSharedMemorySize, SMEM_BYTES);
    cudaFuncSetAttribute(mma_gemm<true,  false, true,  false, false>, cudaFuncAttributeMaxDynamicSharedMemorySize, SMEM_BYTES);

    // ---- conversions ----
    k_splitT<<<dim3(TOTAL_D / 32, TOTAL_D / 32), dim3(32, 32)>>>(W, WTh, WTl);
    k_split<<<(B_ROWS * IN_D + 255) / 256, 256>>>(x,  xh,  xl,  B_ROWS * IN_D, B_ROWS * IN_D);
    k_split<<<(S_D * IN_D + 255) / 256,   256>>>(Wp, Wph, Wpl, S_D * IN_D,    S_D * IN_D);
    k_split<<<(1024 * OD_D + 255) / 256,  256>>>(Wo, Woh, Wol, NC_D * OD_D,   1024 * OD_D);

    // ---- E = x @ Wp^T + bp : write E fp32 (pre-relu) + relu(E) split ----
    mma_gemm<true, false, true, true, true><<<dim3(8, 16), 128, SMEM_BYTES>>>(
        xh, xl, IN_D, Wph, Wpl, IN_D, IN_D, S_D,
        E, S_D, Eh, El, S_D, bp, nullptr, 0);

    // ---- t=1 : Z2 = relu(relu(E) @ W[0:1024,:])  (K=1024) ----
    mma_gemm<false, false, false, true, true><<<dim3(32, 16), 128, SMEM_BYTES>>>(
        Eh, El, S_D, WTh, WTl, TOTAL_D, S_D, TOTAL_D,
        nullptr, 0, Zah, Zal, TOTAL_D, nullptr, nullptr, 0);

    // ---- t=2..8 : full steps (inject E at t=5) ----
    bf16 *ch = Zah, *cl = Zal, *nh = Zbh, *nl = Zbl;
    for (int t = 2; t <= 8; t++) {
        if (t == 5) {
            mma_gemm<false, true, false, true, true><<<dim3(32, 16), 128, SMEM_BYTES>>>(
                ch, cl, TOTAL_D, WTh, WTl, TOTAL_D, TOTAL_D, TOTAL_D,
                nullptr, 0, nh, nl, TOTAL_D, nullptr, E, S_D);
        } else {
            mma_gemm<false, false, false, true, true><<<dim3(32, 16), 128, SMEM_BYTES>>>(
                ch, cl, TOTAL_D, WTh, WTl, TOTAL_D, TOTAL_D, TOTAL_D,
                nullptr, 0, nh, nl, TOTAL_D, nullptr, nullptr, 0);
        }
        bf16* t1 = ch; ch = nh; nh = t1;
        bf16* t2 = cl; cl = nl; nl = t2;
    }

    // ---- t=9 : only the O-slice (N=1024) ----
    mma_gemm<false, false, false, true, true><<<dim3(8, 16), 128, SMEM_BYTES>>>(
        ch, cl, TOTAL_D,
        WTh + (size_t)O_OFF * TOTAL_D, WTl + (size_t)O_OFF * TOTAL_D, TOTAL_D,
        TOTAL_D, OD_D,
        nullptr, 0, Oh, Ol, OD_D, nullptr, nullptr, 0);

    // ---- out = Z10_O @ Wo^T + bo  (Nvalid=1000) ----
    mma_gemm<true, false, true, false, false><<<dim3(8, 16), 128, SMEM_BYTES>>>(
        Oh, Ol, OD_D, Woh, Wol, OD_D, OD_D, NC_D,
        (float*)d_out, NC_D, nullptr, nullptr, 0, bo, nullptr, 0);
}